// round 3
// baseline (speedup 1.0000x reference)
#include <cuda_runtime.h>

// Problem constants (fixed shapes from reference)
#define BB   8
#define HH   64
#define WW   64
#define CC   256
#define RED  64
#define GG   16
#define EE   144        // kk*G
#define NPIX (BB*HH*WW) // 32768

// wgt scratch: [NPIX][144] fp32 = 18.9 MB
__device__ float g_wgt[(size_t)NPIX * EE];

// ---- packed f32x2 helpers (Blackwell) ----
__device__ __forceinline__ unsigned long long pack2(float lo, float hi) {
    unsigned long long r;
    asm("mov.b64 %0, {%1, %2};" : "=l"(r) : "f"(lo), "f"(hi));
    return r;
}
__device__ __forceinline__ void unpack2(unsigned long long v, float& lo, float& hi) {
    asm("mov.b64 {%0, %1}, %2;" : "=f"(lo), "=f"(hi) : "l"(v));
}
__device__ __forceinline__ void ffma2(unsigned long long& d, unsigned long long a, unsigned long long b) {
    asm("fma.rn.f32x2 %0, %1, %2, %0;" : "+l"(d) : "l"(a), "l"(b));
}

// =====================================================================
// Kernel 1: wgt = (x @ W1 + b1) @ W2 + b2   -> g_wgt [NPIX][144]
// Block: 256 threads, 64 pixels (rows). Grid: 512.
// smem floats: W1s[256*64] | xs[64*260] | W2s[64*144] | ts[64*68]
// =====================================================================
#define XS1 260
#define TS1 68
#define SM1_FLOATS (16384 + 64*XS1 + 64*144 + 64*TS1)

__global__ void __launch_bounds__(256, 1) wgt_kernel(
    const float* __restrict__ x,
    const float* __restrict__ W1, const float* __restrict__ b1,
    const float* __restrict__ W2, const float* __restrict__ b2)
{
    extern __shared__ float sm[];
    float* W1s = sm;                 // [256][64]
    float* xs  = sm + 16384;         // [64][260]
    float* W2s = xs + 64 * XS1;      // [64][144]
    float* ts  = W2s + 64 * 144;     // [64][68]

    const int tid  = threadIdx.x;
    const int pix0 = blockIdx.x * 64;

    // --- load W1 (4096 f4), W2 (2304 f4), x tile (4096 f4) ---
    {
        const float4* src = (const float4*)W1;
        float4* dst = (float4*)W1s;
        #pragma unroll
        for (int i = tid; i < 4096; i += 256) dst[i] = src[i];
    }
    {
        const float4* src = (const float4*)W2;
        float4* dst = (float4*)W2s;
        #pragma unroll
        for (int i = tid; i < 2304; i += 256) dst[i] = src[i];
    }
    {
        const float4* src = (const float4*)(x + (size_t)pix0 * CC);
        for (int i = tid; i < 4096; i += 256) {
            int r = i >> 6, c4 = i & 63;
            *(float4*)&xs[r * XS1 + c4 * 4] = src[i];
        }
    }
    __syncthreads();

    // --- Stage A: t[64][64] = xs @ W1 + b1  (f32x2 packed over col-pairs) ---
    {
        const int pg = tid >> 3, tx = tid & 7;
        const int p0 = pg * 2;
        const int d  = tx * 8;

        unsigned long long acc0[4], acc1[4];
        #pragma unroll
        for (int j = 0; j < 4; j++) {
            unsigned long long bv = pack2(b1[d + 2*j], b1[d + 2*j + 1]);
            acc0[j] = bv; acc1[j] = bv;
        }
        const float* x0 = &xs[p0 * XS1];
        const float* x1 = x0 + XS1;

        #pragma unroll 4
        for (int k = 0; k < 256; k++) {
            float a0s = x0[k], a1s = x1[k];
            unsigned long long a0 = pack2(a0s, a0s);
            unsigned long long a1 = pack2(a1s, a1s);
            const ulonglong2* wrow = (const ulonglong2*)&W1s[k * 64 + d];
            ulonglong2 wA = wrow[0];
            ulonglong2 wB = wrow[1];
            ffma2(acc0[0], a0, wA.x); ffma2(acc0[1], a0, wA.y);
            ffma2(acc0[2], a0, wB.x); ffma2(acc0[3], a0, wB.y);
            ffma2(acc1[0], a1, wA.x); ffma2(acc1[1], a1, wA.y);
            ffma2(acc1[2], a1, wB.x); ffma2(acc1[3], a1, wB.y);
        }
        #pragma unroll
        for (int j = 0; j < 4; j++) {
            *(unsigned long long*)&ts[p0 * TS1 + d + 2*j]       = acc0[j];
            *(unsigned long long*)&ts[(p0 + 1) * TS1 + d + 2*j] = acc1[j];
        }
    }
    __syncthreads();

    // --- Stage B: wgt[64][144] = ts @ W2 + b2 ---
    {
        const int p  = tid >> 2, cq = tid & 3;
        const int c0 = cq * 36;

        unsigned long long acc[18];
        #pragma unroll
        for (int j = 0; j < 18; j++)
            acc[j] = pack2(b2[c0 + 2*j], b2[c0 + 2*j + 1]);

        const float* trow = &ts[p * TS1];
        #pragma unroll 2
        for (int k = 0; k < 64; k++) {
            float as = trow[k];
            unsigned long long a = pack2(as, as);
            const ulonglong2* wrow = (const ulonglong2*)&W2s[k * 144 + c0];
            #pragma unroll
            for (int u = 0; u < 9; u++) {
                ulonglong2 w = wrow[u];
                ffma2(acc[2*u],     a, w.x);
                ffma2(acc[2*u + 1], a, w.y);
            }
        }
        float* orow = &g_wgt[(size_t)(pix0 + p) * EE + c0];
        #pragma unroll
        for (int j = 0; j < 18; j++)
            *(unsigned long long*)&orow[2*j] = acc[j];
    }
}

// =====================================================================
// Kernel 2: involution with scrambled group mapping.
// out[b,h,w,oc] = sum_{k2<9} wgt[pix][g*9+k2] * x_pad[b, h+i-1, w+j-1, ch]
//   with f = g*144 + gc*9 + k2, n=f>>8, (i,j)=(n/3,n%3), ch=f&255, oc=g*16+gc
// Block: 8x8 pixel tile, 256 threads. Grid: 512 (8 batches * 64 tiles).
// smem floats: xs[100][260] halo tile | ws[64][148] wgt tile
// =====================================================================
#define XS2 260
#define WS2 148
#define SM2_FLOATS (100*XS2 + 64*WS2)

__global__ void __launch_bounds__(256, 1) invo_kernel(
    const float* __restrict__ x, float* __restrict__ out)
{
    extern __shared__ float sm[];
    float* xs = sm;                  // [100][260] (10x10 halo, 256 ch)
    float* ws = sm + 100 * XS2;      // [64][148]

    const int tid = threadIdx.x;
    const int blk = blockIdx.x;
    const int b  = blk >> 6;
    const int ty = (blk >> 3) & 7;
    const int tw = blk & 7;
    const int h0 = ty * 8, w0 = tw * 8;

    // --- halo load: 100 pixel slots x 64 float4 (zero-pad OOB) ---
    for (int i = tid; i < 6400; i += 256) {
        int slot = i >> 6, c4 = i & 63;
        int py = slot / 10, px = slot - py * 10;
        int gh = h0 + py - 1, gw = w0 + px - 1;
        float4 v = make_float4(0.f, 0.f, 0.f, 0.f);
        if ((unsigned)gh < 64u && (unsigned)gw < 64u) {
            v = *(const float4*)(x + ((size_t)((b * 64 + gh) * 64 + gw)) * CC + c4 * 4);
        }
        *(float4*)&xs[slot * XS2 + c4 * 4] = v;
    }
    // --- wgt tile load: 64 x 36 float4 ---
    for (int i = tid; i < 2304; i += 256) {
        int p = i / 36, c4 = i - p * 36;
        int py = p >> 3, px = p & 7;
        int gpix = (b * 64 + h0 + py) * 64 + w0 + px;
        *(float4*)&ws[p * WS2 + c4 * 4] =
            *(const float4*)&g_wgt[(size_t)gpix * EE + c4 * 4];
    }
    __syncthreads();

    const int lane = tid & 31, warp = tid >> 5;
    // warp handles g = {warp, warp+8}; lanes span pixels -> conflict-free LDS.128
    #pragma unroll
    for (int gi = 0; gi < 2; gi++) {
        const int g = warp + 8 * gi;
        #pragma unroll
        for (int pi = 0; pi < 2; pi++) {
            const int p  = lane + 32 * pi;
            const int py = p >> 3, px = p & 7;

            float wr[9];
            #pragma unroll
            for (int k2 = 0; k2 < 9; k2++) wr[k2] = ws[p * WS2 + g * 9 + k2];

            const int gpix = (b * 64 + h0 + py) * 64 + w0 + px;
            float* orow = out + (size_t)gpix * CC + g * 16;

            #pragma unroll
            for (int gcc = 0; gcc < 4; gcc++) {
                const int f0 = g * 144 + gcc * 36;
                float bf[36];
                #pragma unroll
                for (int u = 0; u < 9; u++) {
                    int f  = f0 + 4 * u;
                    int n  = f >> 8;      // neighbor 0..8 (constant within a float4)
                    int ch = f & 255;
                    int ni = n / 3, nj = n - ni * 3;
                    int pix = (py + ni) * 10 + (px + nj);
                    *(float4*)&bf[4 * u] = *(const float4*)&xs[pix * XS2 + ch];
                }
                float o0 = 0.f, o1 = 0.f, o2 = 0.f, o3 = 0.f;
                #pragma unroll
                for (int k2 = 0; k2 < 9; k2++) {
                    o0 = fmaf(wr[k2], bf[k2],      o0);
                    o1 = fmaf(wr[k2], bf[9 + k2],  o1);
                    o2 = fmaf(wr[k2], bf[18 + k2], o2);
                    o3 = fmaf(wr[k2], bf[27 + k2], o3);
                }
                *(float4*)&orow[gcc * 4] = make_float4(o0, o1, o2, o3);
            }
        }
    }
}

extern "C" void kernel_launch(void* const* d_in, const int* in_sizes, int n_in,
                              void* d_out, int out_size) {
    const float* x  = (const float*)d_in[0];
    const float* W1 = (const float*)d_in[1];
    const float* b1 = (const float*)d_in[2];
    const float* W2 = (const float*)d_in[3];
    const float* b2 = (const float*)d_in[4];
    float* out = (float*)d_out;

    const int SM1 = SM1_FLOATS * 4;  // 186,368 B
    const int SM2 = SM2_FLOATS * 4;  // 141,888 B
    cudaFuncSetAttribute(wgt_kernel,  cudaFuncAttributeMaxDynamicSharedMemorySize, SM1);
    cudaFuncSetAttribute(invo_kernel, cudaFuncAttributeMaxDynamicSharedMemorySize, SM2);

    wgt_kernel<<<512, 256, SM1>>>(x, W1, b1, W2, b2);
    invo_kernel<<<512, 256, SM2>>>(x, out);
}

// round 4
// speedup vs baseline: 1.3148x; 1.3148x over previous
#include <cuda_runtime.h>

// Fixed shapes: B=8, H=W=64, C=256, red=64, G=16, GC=16, kk=9, E=144
#define XS  260   // halo row stride (floats), 100 rows
#define W2S 148   // W2 smem row stride
#define TS  68    // t smem row stride

// smem (floats): xs[100*260]=26000 | W1s[256*64]=16384 | W2s[64*148]=9472 | ts[64*68]=4352
#define SM_FLOATS (100*XS + 256*64 + 64*W2S + 64*TS)   // 56208 -> 224832 B

// ---- packed f32x2 helpers (Blackwell) ----
__device__ __forceinline__ unsigned long long pack2(float lo, float hi) {
    unsigned long long r;
    asm("mov.b64 %0, {%1, %2};" : "=l"(r) : "f"(lo), "f"(hi));
    return r;
}
__device__ __forceinline__ void unpack2(unsigned long long v, float& lo, float& hi) {
    asm("mov.b64 {%0, %1}, %2;" : "=f"(lo), "=f"(hi) : "l"(v));
}
__device__ __forceinline__ void ffma2(unsigned long long& d, unsigned long long a, unsigned long long b) {
    asm("fma.rn.f32x2 %0, %1, %2, %0;" : "+l"(d) : "l"(a), "l"(b));
}

__global__ void __launch_bounds__(256, 1) invo_fused(
    const float* __restrict__ x,
    const float* __restrict__ W1, const float* __restrict__ b1,
    const float* __restrict__ W2, const float* __restrict__ b2,
    float* __restrict__ out)
{
    extern __shared__ float sm[];
    float* xs  = sm;                 // [100][XS]  10x10 halo, 256 ch
    float* W1s = sm + 100 * XS;      // [256][64]
    float* W2s = W1s + 256 * 64;     // [64][W2S]
    float* ts  = W2s + 64 * W2S;     // [64][TS]

    const int tid = threadIdx.x;
    const int blk = blockIdx.x;
    const int b  = blk >> 6;
    const int ty = (blk >> 3) & 7;
    const int tw = blk & 7;
    const int h0 = ty * 8, w0 = tw * 8;

    // ---- cooperative loads ----
    {   // W1 [256][64] : 4096 float4
        const float4* src = (const float4*)W1;
        float4* dst = (float4*)W1s;
        for (int i = tid; i < 4096; i += 256) dst[i] = src[i];
    }
    {   // W2 [64][144] -> padded rows of W2S : 2304 float4
        const float4* src = (const float4*)W2;
        for (int i = tid; i < 2304; i += 256) {
            int r = i / 36, c4 = i - r * 36;
            *(float4*)&W2s[r * W2S + c4 * 4] = src[i];
        }
    }
    {   // halo: 100 pixel slots x 64 float4, zero-padded OOB
        for (int i = tid; i < 6400; i += 256) {
            int slot = i >> 6, c4 = i & 63;
            int py = slot / 10, px = slot - py * 10;
            int gh = h0 + py - 1, gw = w0 + px - 1;
            float4 v = make_float4(0.f, 0.f, 0.f, 0.f);
            if ((unsigned)gh < 64u && (unsigned)gw < 64u)
                v = *(const float4*)(x + ((size_t)((b * 64 + gh) * 64 + gw)) * 256 + c4 * 4);
            *(float4*)&xs[slot * XS + c4 * 4] = v;
        }
    }
    __syncthreads();

    // ---- Stage A: t[64][64] = x_tile @ W1 + b1 ----
    {
        const int pg = tid >> 3, tx = tid & 7;   // 32 pixel-pairs x 8 col-octets
        const int d  = tx * 8;
        const int p0 = pg * 2;
        const int py = p0 >> 3, px = p0 & 7;     // px even
        const float* a0p = &xs[((py + 1) * 10 + px + 1) * XS];
        const float* a1p = a0p + XS;

        unsigned long long acc0[4], acc1[4];
        #pragma unroll
        for (int j = 0; j < 4; j++) {
            unsigned long long bv = pack2(b1[d + 2*j], b1[d + 2*j + 1]);
            acc0[j] = bv; acc1[j] = bv;
        }
        #pragma unroll 4
        for (int k = 0; k < 256; k++) {
            float a0s = a0p[k], a1s = a1p[k];
            unsigned long long a0 = pack2(a0s, a0s);
            unsigned long long a1 = pack2(a1s, a1s);
            const ulonglong2* wrow = (const ulonglong2*)&W1s[k * 64 + d];
            ulonglong2 wA = wrow[0];
            ulonglong2 wB = wrow[1];
            ffma2(acc0[0], a0, wA.x); ffma2(acc0[1], a0, wA.y);
            ffma2(acc0[2], a0, wB.x); ffma2(acc0[3], a0, wB.y);
            ffma2(acc1[0], a1, wA.x); ffma2(acc1[1], a1, wA.y);
            ffma2(acc1[2], a1, wB.x); ffma2(acc1[3], a1, wB.y);
        }
        #pragma unroll
        for (int j = 0; j < 4; j++) {
            *(unsigned long long*)&ts[p0 * TS + d + 2*j]       = acc0[j];
            *(unsigned long long*)&ts[(p0 + 1) * TS + d + 2*j] = acc1[j];
        }
    }
    __syncthreads();

    // ---- Stage B: wgt[p][g*9 + j] = t @ W2 + b2 (kept in registers) ----
    const int g  = tid & 15;     // group owned by this thread
    const int pq = tid >> 4;     // pixel quad: pixels pq*4 .. pq*4+3

    unsigned long long acc2[4][4];   // [pixel][col-pair j=(0,1)(2,3)(4,5)(6,7)]
    float accs[4];                   // j = 8
    {
        unsigned long long bv[4];
        #pragma unroll
        for (int jj = 0; jj < 4; jj++) bv[jj] = pack2(b2[g*9 + 2*jj], b2[g*9 + 2*jj + 1]);
        float bs = b2[g*9 + 8];
        #pragma unroll
        for (int i = 0; i < 4; i++) {
            #pragma unroll
            for (int jj = 0; jj < 4; jj++) acc2[i][jj] = bv[jj];
            accs[i] = bs;
        }
    }
    {
        const float* t0 = &ts[(pq * 4) * TS];
        #pragma unroll 2
        for (int k = 0; k < 64; k++) {
            const float* wrow = &W2s[k * W2S + g * 9];
            float w0 = wrow[0], w1 = wrow[1], w2 = wrow[2], w3 = wrow[3];
            float w4 = wrow[4], w5 = wrow[5], w6 = wrow[6], w7 = wrow[7];
            float w8 = wrow[8];
            unsigned long long W01 = pack2(w0, w1);
            unsigned long long W23 = pack2(w2, w3);
            unsigned long long W45 = pack2(w4, w5);
            unsigned long long W67 = pack2(w6, w7);
            #pragma unroll
            for (int i = 0; i < 4; i++) {
                float a = t0[i * TS + k];
                unsigned long long A = pack2(a, a);
                ffma2(acc2[i][0], A, W01);
                ffma2(acc2[i][1], A, W23);
                ffma2(acc2[i][2], A, W45);
                ffma2(acc2[i][3], A, W67);
                accs[i] = fmaf(a, w8, accs[i]);
            }
        }
    }
    // no sync needed: only xs is read below, unchanged since first sync

    // ---- Involution: out[p][g*16+gc] = sum_k2 wr[k2] * xs[neigh(f)][ch(f)],
    //      f = g*144 + gc*9 + k2, n = f>>8, ch = f&255 ----
    #pragma unroll
    for (int i = 0; i < 4; i++) {
        const int p  = pq * 4 + i;
        const int py = p >> 3, px = p & 7;

        float wr[9];
        unpack2(acc2[i][0], wr[0], wr[1]);
        unpack2(acc2[i][1], wr[2], wr[3]);
        unpack2(acc2[i][2], wr[4], wr[5]);
        unpack2(acc2[i][3], wr[6], wr[7]);
        wr[8] = accs[i];

        float* orow = out + ((size_t)((b * 64 + h0 + py) * 64 + w0 + px)) * 256 + g * 16;

        #pragma unroll
        for (int gcc = 0; gcc < 4; gcc++) {
            const int f0 = g * 144 + gcc * 36;
            float o[4] = {0.f, 0.f, 0.f, 0.f};
            #pragma unroll
            for (int u = 0; u < 9; u++) {
                int f  = f0 + 4 * u;
                int n  = f >> 8;          // neighbor index (constant within the float4)
                int ch = f & 255;
                int ni = n / 3, nj = n - ni * 3;
                int slot = (py + ni) * 10 + (px + nj);
                float4 v = *(const float4*)&xs[slot * XS + ch];
                // distribute: element j of this float4 -> (gc_local, k2) at compile time
                const int i0 = 4 * u;
                o[(i0 + 0) / 9] = fmaf(wr[(i0 + 0) % 9], v.x, o[(i0 + 0) / 9]);
                o[(i0 + 1) / 9] = fmaf(wr[(i0 + 1) % 9], v.y, o[(i0 + 1) / 9]);
                o[(i0 + 2) / 9] = fmaf(wr[(i0 + 2) % 9], v.z, o[(i0 + 2) / 9]);
                o[(i0 + 3) / 9] = fmaf(wr[(i0 + 3) % 9], v.w, o[(i0 + 3) / 9]);
            }
            *(float4*)&orow[gcc * 4] = make_float4(o[0], o[1], o[2], o[3]);
        }
    }
}

extern "C" void kernel_launch(void* const* d_in, const int* in_sizes, int n_in,
                              void* d_out, int out_size) {
    const float* x  = (const float*)d_in[0];
    const float* W1 = (const float*)d_in[1];
    const float* b1 = (const float*)d_in[2];
    const float* W2 = (const float*)d_in[3];
    const float* b2 = (const float*)d_in[4];
    float* out = (float*)d_out;

    const int SM = SM_FLOATS * 4;   // 224832 B
    cudaFuncSetAttribute(invo_fused, cudaFuncAttributeMaxDynamicSharedMemorySize, SM);
    invo_fused<<<512, 256, SM>>>(x, W1, b1, W2, b2, out);
}